// round 1
// baseline (speedup 1.0000x reference)
#include <cuda_runtime.h>

#define NN 50000
#define DD 128
#define EE 800000
#define EPSV 1e-5f

// ---------------- scratch (device globals: the sanctioned no-alloc workaround) ----
__device__ __align__(16) float g_q [NN*DD];
__device__ __align__(16) float g_k [NN*DD];
__device__ __align__(16) float g_v [NN*DD];
__device__ __align__(16) float g_sp[NN*DD];   // s-projection, overwritten in-place with agg+sp
__device__ __align__(16) float g_h [NN*DD];   // h after WO (+x), then BN1 applied in place
__device__ __align__(16) float g_t [NN*2*DD]; // FFN hidden
__device__ int   g_cnt[NN];
__device__ int   g_rowptr[NN+1];
__device__ int   g_cur[NN];
__device__ int   g_srcs[EE];
__device__ __align__(16) float g_sums [4*DD];  // sum1, sq1, sum2, sq2
__device__ __align__(16) float g_scale[2*DD];
__device__ __align__(16) float g_shift[2*DD];

// ---------------- CSR build ----------------
__global__ void zero_kernel() {
    int i = blockIdx.x * blockDim.x + threadIdx.x;
    if (i < NN) g_cnt[i] = 0;
    if (i < 4*DD) g_sums[i] = 0.f;
}

__global__ void hist_kernel(const int* __restrict__ dst) {
    for (int e = blockIdx.x * blockDim.x + threadIdx.x; e < EE; e += gridDim.x * blockDim.x)
        atomicAdd(&g_cnt[dst[e]], 1);
}

__global__ void scan_kernel() {  // 1 block, 1024 threads
    __shared__ int part[1024];
    const int CH = (NN + 1023) / 1024;  // 49
    int t = threadIdx.x;
    int s = 0;
    for (int i = 0; i < CH; i++) {
        int idx = t * CH + i;
        if (idx < NN) s += g_cnt[idx];
    }
    part[t] = s;
    __syncthreads();
    // Hillis-Steele inclusive scan
    for (int off = 1; off < 1024; off <<= 1) {
        int v = (t >= off) ? part[t - off] : 0;
        __syncthreads();
        part[t] += v;
        __syncthreads();
    }
    int base = (t == 0) ? 0 : part[t - 1];
    for (int i = 0; i < CH; i++) {
        int idx = t * CH + i;
        if (idx < NN) {
            g_rowptr[idx] = base;
            g_cur[idx]    = base;
            base += g_cnt[idx];
        }
    }
    if (t == 1023) g_rowptr[NN] = part[1023];
}

__global__ void scatter_kernel(const int* __restrict__ src, const int* __restrict__ dst) {
    for (int e = blockIdx.x * blockDim.x + threadIdx.x; e < EE; e += gridDim.x * blockDim.x) {
        int pos = atomicAdd(&g_cur[dst[e]], 1);
        g_srcs[pos] = src[e];
    }
}

// ---------------- fused attention: one warp per dst node, online softmax ----------
// sp holds x@Ws+bs on entry; on exit holds agg + that (the pre-WO activation).
__global__ void attn_kernel(const float* __restrict__ q, const float* __restrict__ k,
                            const float* __restrict__ v, float* __restrict__ sp)
{
    int warp = (blockIdx.x * blockDim.x + threadIdx.x) >> 5;
    int lane = threadIdx.x & 31;
    if (warp >= NN) return;
    int beg = g_rowptr[warp];
    int end = g_rowptr[warp + 1];

    float4 qv = *(const float4*)(q + (size_t)warp * DD + lane * 4);

    float m = -1e30f, den = 0.f;
    float4 acc = make_float4(0.f, 0.f, 0.f, 0.f);

    for (int i = beg; i < end; i++) {
        int s = g_srcs[i];
        const float* kp = k + (size_t)s * DD + lane * 4;
        float4 kv = *(const float4*)kp;
        float d = qv.x * kv.x + qv.y * kv.y + qv.z * kv.z + qv.w * kv.w;
        #pragma unroll
        for (int o = 16; o; o >>= 1) d += __shfl_xor_sync(0xffffffffu, d, o);
        d *= 0.08838834764831845f;  // 1/sqrt(128)

        float mnew = fmaxf(m, d);
        float r = __expf(m - mnew);
        float p = __expf(d - mnew);
        den = den * r + p;
        float4 vv = *(const float4*)(v + (size_t)s * DD + lane * 4);
        acc.x = acc.x * r + p * vv.x;
        acc.y = acc.y * r + p * vv.y;
        acc.z = acc.z * r + p * vv.z;
        acc.w = acc.w * r + p * vv.w;
        m = mnew;
    }

    float inv = (end > beg) ? (1.f / den) : 0.f;
    float* spp = sp + (size_t)warp * DD + lane * 4;
    float4 spv = *(const float4*)spp;
    float4 o;
    o.x = acc.x * inv + spv.x;
    o.y = acc.y * inv + spv.y;
    o.z = acc.z * inv + spv.z;
    o.w = acc.w * inv + spv.w;
    *(float4*)spp = o;
}

// ---------------- fp32 SGEMM: C[M,NC] = A[M,K] @ W[K,NC] + bias (+ add) (relu?) ----
__global__ __launch_bounds__(256, 2)
void sgemm_kernel(const float* __restrict__ A, const float* __restrict__ W,
                  const float* __restrict__ bias, const float* __restrict__ add,
                  float* __restrict__ C, int M, int K, int NC, int relu)
{
    __shared__ float As[2][8][128];
    __shared__ float Bs[2][8][128];
    const int tid = threadIdx.x;
    const int rowBase = blockIdx.x * 128;
    const int colBase = blockIdx.y * 128;
    const int arow = tid >> 1;
    const int acol = (tid & 1) << 2;
    const int brow = tid >> 5;
    const int bcol = (tid & 31) << 2;
    const int tx = (tid & 15) << 3;
    const int ty = (tid >> 4) << 3;

    float acc[8][8];
    #pragma unroll
    for (int i = 0; i < 8; i++)
        #pragma unroll
        for (int j = 0; j < 8; j++) acc[i][j] = 0.f;

    // prologue: load k-block 0 into buf 0
    {
        int gr = rowBase + arow;
        float4 av = make_float4(0.f, 0.f, 0.f, 0.f);
        if (gr < M) av = *(const float4*)(A + (size_t)gr * K + acol);
        As[0][acol + 0][arow] = av.x;
        As[0][acol + 1][arow] = av.y;
        As[0][acol + 2][arow] = av.z;
        As[0][acol + 3][arow] = av.w;
        float4 bv = *(const float4*)(W + (size_t)brow * NC + colBase + bcol);
        *(float4*)&Bs[0][brow][bcol] = bv;
    }
    __syncthreads();

    const int nk = K >> 3;
    for (int t = 0; t < nk; t++) {
        int buf = t & 1;
        if (t + 1 < nk) {
            int k0 = (t + 1) << 3;
            int gr = rowBase + arow;
            float4 av = make_float4(0.f, 0.f, 0.f, 0.f);
            if (gr < M) av = *(const float4*)(A + (size_t)gr * K + k0 + acol);
            As[buf ^ 1][acol + 0][arow] = av.x;
            As[buf ^ 1][acol + 1][arow] = av.y;
            As[buf ^ 1][acol + 2][arow] = av.z;
            As[buf ^ 1][acol + 3][arow] = av.w;
            float4 bv = *(const float4*)(W + (size_t)(k0 + brow) * NC + colBase + bcol);
            *(float4*)&Bs[buf ^ 1][brow][bcol] = bv;
        }
        #pragma unroll
        for (int kk = 0; kk < 8; kk++) {
            float a[8], b[8];
            *(float4*)&a[0] = *(const float4*)&As[buf][kk][ty];
            *(float4*)&a[4] = *(const float4*)&As[buf][kk][ty + 4];
            *(float4*)&b[0] = *(const float4*)&Bs[buf][kk][tx];
            *(float4*)&b[4] = *(const float4*)&Bs[buf][kk][tx + 4];
            #pragma unroll
            for (int i = 0; i < 8; i++)
                #pragma unroll
                for (int j = 0; j < 8; j++) acc[i][j] += a[i] * b[j];
        }
        __syncthreads();
    }

    #pragma unroll
    for (int i = 0; i < 8; i++) {
        int r = rowBase + ty + i;
        if (r >= M) continue;
        #pragma unroll
        for (int j = 0; j < 8; j += 4) {
            int c = colBase + tx + j;
            float4 o;
            o.x = acc[i][j]; o.y = acc[i][j + 1]; o.z = acc[i][j + 2]; o.w = acc[i][j + 3];
            float4 bb = *(const float4*)(bias + c);
            o.x += bb.x; o.y += bb.y; o.z += bb.z; o.w += bb.w;
            if (add) {
                float4 ad = *(const float4*)(add + (size_t)r * NC + c);
                o.x += ad.x; o.y += ad.y; o.z += ad.z; o.w += ad.w;
            }
            if (relu) {
                o.x = fmaxf(o.x, 0.f); o.y = fmaxf(o.y, 0.f);
                o.z = fmaxf(o.z, 0.f); o.w = fmaxf(o.w, 0.f);
            }
            *(float4*)(C + (size_t)r * NC + c) = o;
        }
    }
}

// ---------------- BatchNorm ----------------
__global__ void bnstats_kernel(const float* __restrict__ h, int which) {
    int c = threadIdx.x;  // 128 threads
    float s = 0.f, s2 = 0.f;
    for (int r = blockIdx.x; r < NN; r += gridDim.x) {
        float vv = h[(size_t)r * DD + c];
        s += vv;
        s2 += vv * vv;
    }
    atomicAdd(&g_sums[which * 2 * DD + c], s);
    atomicAdd(&g_sums[which * 2 * DD + DD + c], s2);
}

__global__ void bnfin_kernel(const float* __restrict__ g, const float* __restrict__ be, int which) {
    int c = threadIdx.x;
    float mu  = g_sums[which * 2 * DD + c] / (float)NN;
    float var = g_sums[which * 2 * DD + DD + c] / (float)NN - mu * mu;
    float sc = g[c] * rsqrtf(var + EPSV);
    g_scale[which * DD + c] = sc;
    g_shift[which * DD + c] = be[c] - mu * sc;
}

__global__ void bnapply_kernel(float* __restrict__ h, int which) {
    const int total = NN * DD / 4;
    for (int i = blockIdx.x * blockDim.x + threadIdx.x; i < total; i += gridDim.x * blockDim.x) {
        float4 vv = ((float4*)h)[i];
        int cb = (i & 31) << 2;  // (i*4) % 128
        float4 sc = *(const float4*)&g_scale[which * DD + cb];
        float4 sh = *(const float4*)&g_shift[which * DD + cb];
        vv.x = vv.x * sc.x + sh.x;
        vv.y = vv.y * sc.y + sh.y;
        vv.z = vv.z * sc.z + sh.z;
        vv.w = vv.w * sc.w + sh.w;
        ((float4*)h)[i] = vv;
    }
}

// ---------------- launch ----------------
extern "C" void kernel_launch(void* const* d_in, const int* in_sizes, int n_in,
                              void* d_out, int out_size)
{
    const float* x  = (const float*)d_in[0];
    const int*   ei = (const int*)  d_in[1];
    const float *Wq = (const float*)d_in[2],  *bq = (const float*)d_in[3];
    const float *Wk = (const float*)d_in[4],  *bk = (const float*)d_in[5];
    const float *Wv = (const float*)d_in[6],  *bv = (const float*)d_in[7];
    const float *Ws = (const float*)d_in[8],  *bs = (const float*)d_in[9];
    const float *WO = (const float*)d_in[10], *bO = (const float*)d_in[11];
    const float *W1 = (const float*)d_in[12], *b1 = (const float*)d_in[13];
    const float *W2 = (const float*)d_in[14], *b2 = (const float*)d_in[15];
    const float *g1 = (const float*)d_in[16], *be1 = (const float*)d_in[17];
    const float *g2 = (const float*)d_in[18], *be2 = (const float*)d_in[19];
    float* out = (float*)d_out;

    const int* src = ei;
    const int* dst = ei + EE;

    float *q, *k, *v, *sp, *h, *t;
    cudaGetSymbolAddress((void**)&q,  g_q);
    cudaGetSymbolAddress((void**)&k,  g_k);
    cudaGetSymbolAddress((void**)&v,  g_v);
    cudaGetSymbolAddress((void**)&sp, g_sp);
    cudaGetSymbolAddress((void**)&h,  g_h);
    cudaGetSymbolAddress((void**)&t,  g_t);

    const int MB = (NN + 127) / 128;  // 391

    // CSR build
    zero_kernel<<<(NN + 255) / 256, 256>>>();
    hist_kernel<<<512, 256>>>(dst);
    scan_kernel<<<1, 1024>>>();
    scatter_kernel<<<512, 256>>>(src, dst);

    // projections
    sgemm_kernel<<<dim3(MB, 1), 256>>>(x, Wq, bq, nullptr, q,  NN, DD, DD, 0);
    sgemm_kernel<<<dim3(MB, 1), 256>>>(x, Wk, bk, nullptr, k,  NN, DD, DD, 0);
    sgemm_kernel<<<dim3(MB, 1), 256>>>(x, Wv, bv, nullptr, v,  NN, DD, DD, 0);
    sgemm_kernel<<<dim3(MB, 1), 256>>>(x, Ws, bs, nullptr, sp, NN, DD, DD, 0);

    // attention (writes agg + sp into sp)
    attn_kernel<<<(NN * 32 + 255) / 256, 256>>>(q, k, v, sp);

    // h = sp @ WO + bO + x
    sgemm_kernel<<<dim3(MB, 1), 256>>>(sp, WO, bO, x, h, NN, DD, DD, 0);

    // BN1 (in place on h)
    bnstats_kernel<<<256, 128>>>(h, 0);
    bnfin_kernel<<<1, 128>>>(g1, be1, 0);
    bnapply_kernel<<<512, 256>>>(h, 0);

    // FFN: t = relu(h @ W1 + b1); out = t @ W2 + b2 + h
    sgemm_kernel<<<dim3(MB, 2), 256>>>(h, W1, b1, nullptr, t, NN, DD, 2 * DD, 1);
    sgemm_kernel<<<dim3(MB, 1), 256>>>(t, W2, b2, h, out, NN, 2 * DD, DD, 0);

    // BN2 (in place on out)
    bnstats_kernel<<<256, 128>>>(out, 1);
    bnfin_kernel<<<1, 128>>>(g2, be2, 1);
    bnapply_kernel<<<512, 256>>>(out, 1);
}

// round 2
// speedup vs baseline: 1.8296x; 1.8296x over previous
#include <cuda_runtime.h>

#define NN 50000
#define DD 128
#define EE 800000
#define EPSV 1e-5f

// ---------------- scratch ----------------
__device__ __align__(16) float g_q [NN*DD];
__device__ __align__(16) float g_k [NN*DD];
__device__ __align__(16) float g_v [NN*DD];
__device__ __align__(16) float g_sp[NN*DD];
__device__ __align__(16) float g_h [NN*DD];
__device__ __align__(16) float g_t [NN*2*DD];
__device__ int   g_cnt[NN];
__device__ int   g_rowptr[NN+1];
__device__ int   g_cur[NN];
__device__ int   g_srcs[EE];
__device__ __align__(16) float g_sums [4*DD];
__device__ __align__(16) float g_scale[2*DD];
__device__ __align__(16) float g_shift[2*DD];

// ---------------- CSR build ----------------
__global__ void zero_kernel() {
    int i = blockIdx.x * blockDim.x + threadIdx.x;
    if (i < NN) g_cnt[i] = 0;
    if (i < 4*DD) g_sums[i] = 0.f;
}

__global__ void hist_kernel(const int* __restrict__ dst) {
    for (int e = blockIdx.x * blockDim.x + threadIdx.x; e < EE; e += gridDim.x * blockDim.x)
        atomicAdd(&g_cnt[dst[e]], 1);
}

__global__ void scan_kernel() {
    __shared__ int part[1024];
    const int CH = (NN + 1023) / 1024;
    int t = threadIdx.x;
    int s = 0;
    for (int i = 0; i < CH; i++) {
        int idx = t * CH + i;
        if (idx < NN) s += g_cnt[idx];
    }
    part[t] = s;
    __syncthreads();
    for (int off = 1; off < 1024; off <<= 1) {
        int v = (t >= off) ? part[t - off] : 0;
        __syncthreads();
        part[t] += v;
        __syncthreads();
    }
    int base = (t == 0) ? 0 : part[t - 1];
    for (int i = 0; i < CH; i++) {
        int idx = t * CH + i;
        if (idx < NN) {
            g_rowptr[idx] = base;
            g_cur[idx]    = base;
            base += g_cnt[idx];
        }
    }
    if (t == 1023) g_rowptr[NN] = part[1023];
}

__global__ void scatter_kernel(const int* __restrict__ src, const int* __restrict__ dst) {
    for (int e = blockIdx.x * blockDim.x + threadIdx.x; e < EE; e += gridDim.x * blockDim.x) {
        int pos = atomicAdd(&g_cur[dst[e]], 1);
        g_srcs[pos] = src[e];
    }
}

// ---------------- attention: one warp per dst node, online softmax ----------
__global__ void attn_kernel(const float* __restrict__ q, const float* __restrict__ k,
                            const float* __restrict__ v, float* __restrict__ sp)
{
    int warp = (blockIdx.x * blockDim.x + threadIdx.x) >> 5;
    int lane = threadIdx.x & 31;
    if (warp >= NN) return;
    int beg = g_rowptr[warp];
    int end = g_rowptr[warp + 1];

    float4 qv = *(const float4*)(q + (size_t)warp * DD + lane * 4);

    float m = -1e30f, den = 0.f;
    float4 acc = make_float4(0.f, 0.f, 0.f, 0.f);

    for (int i = beg; i < end; i++) {
        int s = g_srcs[i];
        float4 kv = *(const float4*)(k + (size_t)s * DD + lane * 4);
        float d = qv.x * kv.x + qv.y * kv.y + qv.z * kv.z + qv.w * kv.w;
        #pragma unroll
        for (int o = 16; o; o >>= 1) d += __shfl_xor_sync(0xffffffffu, d, o);
        d *= 0.08838834764831845f;

        float mnew = fmaxf(m, d);
        float r = __expf(m - mnew);
        float p = __expf(d - mnew);
        den = den * r + p;
        float4 vv = *(const float4*)(v + (size_t)s * DD + lane * 4);
        acc.x = acc.x * r + p * vv.x;
        acc.y = acc.y * r + p * vv.y;
        acc.z = acc.z * r + p * vv.z;
        acc.w = acc.w * r + p * vv.w;
        m = mnew;
    }

    float inv = (end > beg) ? (1.f / den) : 0.f;
    float* spp = sp + (size_t)warp * DD + lane * 4;
    float4 spv = *(const float4*)spp;
    float4 o;
    o.x = acc.x * inv + spv.x;
    o.y = acc.y * inv + spv.y;
    o.z = acc.z * inv + spv.z;
    o.w = acc.w * inv + spv.w;
    *(float4*)spp = o;
}

// ---------------- tf32 tensor-core GEMM ----------------
struct P4 {
    const float* W[4];
    const float* B[4];
    float*       C[4];
};

__device__ __forceinline__ unsigned f2tf(float x) {
    unsigned u;
    asm("cvt.rna.tf32.f32 %0, %1;" : "=r"(u) : "f"(x));
    return u;
}

__device__ __forceinline__ void mma8(float* c, const unsigned* a, const unsigned* b) {
    asm volatile(
        "mma.sync.aligned.m16n8k8.row.col.f32.tf32.tf32.f32 "
        "{%0,%1,%2,%3}, {%4,%5,%6,%7}, {%8,%9}, {%0,%1,%2,%3};\n"
        : "+f"(c[0]), "+f"(c[1]), "+f"(c[2]), "+f"(c[3])
        : "r"(a[0]), "r"(a[1]), "r"(a[2]), "r"(a[3]), "r"(b[0]), "r"(b[1]));
}

// C[M,NC] = A[M,K] @ W[K,NC] + bias (+ add) (relu?)
// BM=128, BN=128, BK=16; 256 threads, 8 warps, warp tile 64x32.
__global__ __launch_bounds__(256)
void gemm_tf32(const float* __restrict__ A, P4 p, const float* __restrict__ add,
               int M, int K, int NC, int relu)
{
    const float* W    = p.W[blockIdx.z];
    const float* bias = p.B[blockIdx.z];
    float*       C    = p.C[blockIdx.z];

    // A: [buf][kt][reg][mt][slot]  (lane-rotated SoA, conflict-free both sides)
    __shared__ float As[2][2][4][8][32];
    // B: [buf][k][n] row-major, padded to 132
    __shared__ float Bs[2][16][132];

    const int tid  = threadIdx.x;
    const int lane = tid & 31;
    const int warp = tid >> 5;
    const int wm = warp & 1;     // 2 m-partitions of 64
    const int wn = warp >> 1;    // 4 n-partitions of 32
    const int rowBase = blockIdx.x * 128;
    const int colBase = blockIdx.y * 128;

    float acc[4][4][4];
    #pragma unroll
    for (int i = 0; i < 4; i++)
        #pragma unroll
        for (int j = 0; j < 4; j++)
            #pragma unroll
            for (int r = 0; r < 4; r++) acc[i][j][r] = 0.f;

    const int arow = tid >> 2;           // 0..63 (+64 for second vector)
    const int acol = (tid & 3) << 2;     // 0,4,8,12
    const int brow = tid >> 5;           // 0..7 (+8 for second vector)
    const int bcol = (tid & 31) << 2;

    const bool aok0 = (rowBase + arow)      < M;
    const bool aok1 = (rowBase + arow + 64) < M;

    const float* Aptr = A + (size_t)(rowBase + arow) * K + acol;
    const float* Wptr = W + (size_t)brow * NC + colBase + bcol;

    const int ntiles = K >> 4;

    // A smem store: element rows r..r (cols acol..acol+3)
    auto stsA = [&](int bf, float4 v, int r) {
        int mt = r >> 4;
        int kt = acol >> 3;
        int ch = (acol >> 2) & 1;
        int rb = (r >> 3) & 1;
        int qq = rb + 2 * ch;
        int g  = kt * 2 + ch;
        int s0 = (r & 7) * 4 + g;
        float* bp = &As[bf][kt][qq][mt][0];
        bp[(s0 + 0) & 31] = __uint_as_float(f2tf(v.x));
        bp[(s0 + 1) & 31] = __uint_as_float(f2tf(v.y));
        bp[(s0 + 2) & 31] = __uint_as_float(f2tf(v.z));
        bp[(s0 + 3) & 31] = __uint_as_float(f2tf(v.w));
    };
    auto stsB = [&](int bf, float4 v, int kk) {
        float4 w;
        w.x = __uint_as_float(f2tf(v.x));
        w.y = __uint_as_float(f2tf(v.y));
        w.z = __uint_as_float(f2tf(v.z));
        w.w = __uint_as_float(f2tf(v.w));
        *(float4*)&Bs[bf][kk][bcol] = w;
    };

    float4 a0v, a1v, b0v, b1v;
    // prologue: tile 0
    a0v = aok0 ? *(const float4*)Aptr                    : make_float4(0, 0, 0, 0);
    a1v = aok1 ? *(const float4*)(Aptr + (size_t)64 * K) : make_float4(0, 0, 0, 0);
    b0v = *(const float4*)Wptr;
    b1v = *(const float4*)(Wptr + (size_t)8 * NC);
    stsA(0, a0v, arow);
    stsA(0, a1v, arow + 64);
    stsB(0, b0v, brow);
    stsB(0, b1v, brow + 8);
    __syncthreads();

    int buf = 0;
    for (int t = 0; t < ntiles; t++) {
        if (t + 1 < ntiles) {
            Aptr += 16;
            Wptr += (size_t)16 * NC;
            a0v = aok0 ? *(const float4*)Aptr                    : make_float4(0, 0, 0, 0);
            a1v = aok1 ? *(const float4*)(Aptr + (size_t)64 * K) : make_float4(0, 0, 0, 0);
            b0v = *(const float4*)Wptr;
            b1v = *(const float4*)(Wptr + (size_t)8 * NC);
        }

        #pragma unroll
        for (int kt = 0; kt < 2; kt++) {
            unsigned af[4][4];
            unsigned bfr[4][2];
            #pragma unroll
            for (int i = 0; i < 4; i++) {
                int mt = wm * 4 + i;
                #pragma unroll
                for (int qq = 0; qq < 4; qq++)
                    af[i][qq] = __float_as_uint(
                        As[buf][kt][qq][mt][(lane + kt * 2 + (qq >> 1)) & 31]);
            }
            #pragma unroll
            for (int j = 0; j < 4; j++) {
                int col = (wn * 4 + j) * 8 + (lane >> 2);
                bfr[j][0] = __float_as_uint(Bs[buf][kt * 8 + (lane & 3)][col]);
                bfr[j][1] = __float_as_uint(Bs[buf][kt * 8 + (lane & 3) + 4][col]);
            }
            #pragma unroll
            for (int i = 0; i < 4; i++)
                #pragma unroll
                for (int j = 0; j < 4; j++)
                    mma8(acc[i][j], af[i], bfr[j]);
        }

        if (t + 1 < ntiles) {
            stsA(buf ^ 1, a0v, arow);
            stsA(buf ^ 1, a1v, arow + 64);
            stsB(buf ^ 1, b0v, brow);
            stsB(buf ^ 1, b1v, brow + 8);
        }
        __syncthreads();
        buf ^= 1;
    }

    // epilogue
    #pragma unroll
    for (int i = 0; i < 4; i++) {
        int r0 = rowBase + wm * 64 + i * 16 + (lane >> 2);
        #pragma unroll
        for (int j = 0; j < 4; j++) {
            int c = colBase + (wn * 4 + j) * 8 + (lane & 3) * 2;
            float2 bb = *(const float2*)(bias + c);
            if (r0 < M) {
                float2 o;
                o.x = acc[i][j][0] + bb.x;
                o.y = acc[i][j][1] + bb.y;
                if (add) {
                    float2 ad = *(const float2*)(add + (size_t)r0 * NC + c);
                    o.x += ad.x; o.y += ad.y;
                }
                if (relu) { o.x = fmaxf(o.x, 0.f); o.y = fmaxf(o.y, 0.f); }
                *(float2*)(C + (size_t)r0 * NC + c) = o;
            }
            int r1 = r0 + 8;
            if (r1 < M) {
                float2 o;
                o.x = acc[i][j][2] + bb.x;
                o.y = acc[i][j][3] + bb.y;
                if (add) {
                    float2 ad = *(const float2*)(add + (size_t)r1 * NC + c);
                    o.x += ad.x; o.y += ad.y;
                }
                if (relu) { o.x = fmaxf(o.x, 0.f); o.y = fmaxf(o.y, 0.f); }
                *(float2*)(C + (size_t)r1 * NC + c) = o;
            }
        }
    }
}

// ---------------- BatchNorm ----------------
__global__ void bnstats_kernel(const float* __restrict__ h, int which) {
    int c = threadIdx.x;
    float s = 0.f, s2 = 0.f;
    for (int r = blockIdx.x; r < NN; r += gridDim.x) {
        float vv = h[(size_t)r * DD + c];
        s += vv;
        s2 += vv * vv;
    }
    atomicAdd(&g_sums[which * 2 * DD + c], s);
    atomicAdd(&g_sums[which * 2 * DD + DD + c], s2);
}

__global__ void bnfin_kernel(const float* __restrict__ g, const float* __restrict__ be, int which) {
    int c = threadIdx.x;
    float mu  = g_sums[which * 2 * DD + c] / (float)NN;
    float var = g_sums[which * 2 * DD + DD + c] / (float)NN - mu * mu;
    float sc = g[c] * rsqrtf(var + EPSV);
    g_scale[which * DD + c] = sc;
    g_shift[which * DD + c] = be[c] - mu * sc;
}

__global__ void bnapply_kernel(float* __restrict__ h, int which) {
    const int total = NN * DD / 4;
    for (int i = blockIdx.x * blockDim.x + threadIdx.x; i < total; i += gridDim.x * blockDim.x) {
        float4 vv = ((float4*)h)[i];
        int cb = (i & 31) << 2;
        float4 sc = *(const float4*)&g_scale[which * DD + cb];
        float4 sh = *(const float4*)&g_shift[which * DD + cb];
        vv.x = vv.x * sc.x + sh.x;
        vv.y = vv.y * sc.y + sh.y;
        vv.z = vv.z * sc.z + sh.z;
        vv.w = vv.w * sc.w + sh.w;
        ((float4*)h)[i] = vv;
    }
}

// ---------------- launch ----------------
extern "C" void kernel_launch(void* const* d_in, const int* in_sizes, int n_in,
                              void* d_out, int out_size)
{
    const float* x  = (const float*)d_in[0];
    const int*   ei = (const int*)  d_in[1];
    const float *Wq = (const float*)d_in[2],  *bq = (const float*)d_in[3];
    const float *Wk = (const float*)d_in[4],  *bk = (const float*)d_in[5];
    const float *Wv = (const float*)d_in[6],  *bv = (const float*)d_in[7];
    const float *Ws = (const float*)d_in[8],  *bs = (const float*)d_in[9];
    const float *WO = (const float*)d_in[10], *bO = (const float*)d_in[11];
    const float *W1 = (const float*)d_in[12], *b1 = (const float*)d_in[13];
    const float *W2 = (const float*)d_in[14], *b2 = (const float*)d_in[15];
    const float *g1 = (const float*)d_in[16], *be1 = (const float*)d_in[17];
    const float *g2 = (const float*)d_in[18], *be2 = (const float*)d_in[19];
    float* out = (float*)d_out;

    const int* src = ei;
    const int* dst = ei + EE;

    float *q, *k, *v, *sp, *h, *t;
    cudaGetSymbolAddress((void**)&q,  g_q);
    cudaGetSymbolAddress((void**)&k,  g_k);
    cudaGetSymbolAddress((void**)&v,  g_v);
    cudaGetSymbolAddress((void**)&sp, g_sp);
    cudaGetSymbolAddress((void**)&h,  g_h);
    cudaGetSymbolAddress((void**)&t,  g_t);

    const int MB = (NN + 127) / 128;  // 391

    // CSR build
    zero_kernel<<<(NN + 255) / 256, 256>>>();
    hist_kernel<<<512, 256>>>(dst);
    scan_kernel<<<1, 1024>>>();
    scatter_kernel<<<512, 256>>>(src, dst);

    // fused Q/K/V/S projections (one launch, z selects weight set)
    {
        P4 p;
        p.W[0] = Wq; p.B[0] = bq; p.C[0] = q;
        p.W[1] = Wk; p.B[1] = bk; p.C[1] = k;
        p.W[2] = Wv; p.B[2] = bv; p.C[2] = v;
        p.W[3] = Ws; p.B[3] = bs; p.C[3] = sp;
        gemm_tf32<<<dim3(MB, 1, 4), 256>>>(x, p, nullptr, NN, DD, DD, 0);
    }

    // attention (writes agg + sp into sp)
    attn_kernel<<<(NN * 32 + 255) / 256, 256>>>(q, k, v, sp);

    // h = sp @ WO + bO + x
    {
        P4 p = {};
        p.W[0] = WO; p.B[0] = bO; p.C[0] = h;
        gemm_tf32<<<dim3(MB, 1, 1), 256>>>(sp, p, x, NN, DD, DD, 0);
    }

    // BN1
    bnstats_kernel<<<256, 128>>>(h, 0);
    bnfin_kernel<<<1, 128>>>(g1, be1, 0);
    bnapply_kernel<<<512, 256>>>(h, 0);

    // FFN
    {
        P4 p = {};
        p.W[0] = W1; p.B[0] = b1; p.C[0] = t;
        gemm_tf32<<<dim3(MB, 2, 1), 256>>>(h, p, nullptr, NN, DD, 2 * DD, 1);
    }
    {
        P4 p = {};
        p.W[0] = W2; p.B[0] = b2; p.C[0] = out;
        gemm_tf32<<<dim3(MB, 1, 1), 256>>>(t, p, h, NN, 2 * DD, DD, 0);
    }

    // BN2
    bnstats_kernel<<<256, 128>>>(out, 1);
    bnfin_kernel<<<1, 128>>>(g2, be2, 1);
    bnapply_kernel<<<512, 256>>>(out, 1);
}